// round 2
// baseline (speedup 1.0000x reference)
#include <cuda_runtime.h>

// LSTMModel: 2-layer LSTM (B=4096, T=256, D=4, H=64) + FC(64->1).
// Strategy: batch-parallel persistent-step kernels.
//   - kernel0: layer-0 LSTM, input projection fused (D=4), writes h1 to scratch.
//   - kernel1: layer-1 LSTM + final FC fused at last timestep.
// Thread t of a 256-thread CTA computes gate row t (i,f,g,o order) for NB=4
// batch elements, with weight rows in registers and h broadcast from smem.
// Inner product uses Blackwell packed fma.rn.f32x2 (2x fp32 throughput),
// packed along K so operands are natural aligned register pairs (no MOVs).

#define B_TOTAL 4096
#define T_STEPS 256
#define D_IN    4
#define HDIM    64
#define GDIM    256   // 4*H
#define NB      4     // batch elements per block

typedef unsigned long long u64;

// 268 MB scratch for h1 (layer0 output). Static device global: allowed.
__device__ float g_h1[(size_t)B_TOTAL * T_STEPS * HDIM];

__device__ __forceinline__ u64 pk(float lo, float hi) {
    u64 r; asm("mov.b64 %0,{%1,%2};" : "=l"(r) : "f"(lo), "f"(hi)); return r;
}
__device__ __forceinline__ void upk(u64 v, float& lo, float& hi) {
    asm("mov.b64 {%0,%1},%2;" : "=f"(lo), "=f"(hi) : "l"(v));
}
// d = a*b + c, lanewise on packed f32 pairs (Blackwell FFMA2)
__device__ __forceinline__ u64 f2(u64 a, u64 b, u64 c) {
    u64 d; asm("fma.rn.f32x2 %0,%1,%2,%3;" : "=l"(d) : "l"(a), "l"(b), "l"(c));
    return d;
}
__device__ __forceinline__ float sigf(float x) {
    return 1.0f / (1.0f + __expf(-x));
}

// ---------------------------------------------------------------------------
// Layer 0: x[B,T,4] -> h1[B,T,64]
// ---------------------------------------------------------------------------
__global__ void __launch_bounds__(256) lstm_layer0(
    const float* __restrict__ x, const float* __restrict__ Wih,
    const float* __restrict__ Whh, const float* __restrict__ bih,
    const float* __restrict__ bhh)
{
    __shared__ float x_sm[NB][T_STEPS * D_IN];  // 16 KB, e-major
    __shared__ float h_sm[NB][HDIM];            // 1 KB,  e-major
    __shared__ float g_sm[NB][GDIM];            // 4 KB,  e-major

    const int tid = threadIdx.x;
    const int b0  = blockIdx.x * NB;

    // Weight rows for gate `tid` into registers (as packed K-pairs).
    u64 wih[2];
    u64 whh[32];
    {
        const ulonglong2* wr = (const ulonglong2*)(Wih + tid * D_IN);
        ulonglong2 t = wr[0];
        wih[0] = t.x; wih[1] = t.y;
        const ulonglong2* hr = (const ulonglong2*)(Whh + tid * HDIM);
#pragma unroll
        for (int i = 0; i < 16; i++) {
            ulonglong2 v = hr[i];
            whh[2 * i] = v.x; whh[2 * i + 1] = v.y;
        }
    }
    const float bias = bih[tid] + bhh[tid];

    // Preload all x for this block's 4 batch elements (coalesced, once).
    for (int idx = tid; idx < NB * T_STEPS; idx += 256) {
        int e = idx >> 8;          // /256
        int r = idx & 255;
        ((float4*)x_sm[e])[r] =
            ((const float4*)(x + (size_t)(b0 + e) * T_STEPS * D_IN))[r];
    }
    ((float*)h_sm)[tid] = 0.0f;    // NB*H == 256 == blockDim
    float c_state = 0.0f;
    const int e_up = tid >> 6, j_up = tid & 63;
    float* h1_row = g_h1 + ((size_t)(b0 + e_up) * T_STEPS) * HDIM + j_up;
    __syncthreads();

    for (int s = 0; s < T_STEPS; s++) {
        // ---- gate pre-activation: thread computes row `tid` for all NB elems
        u64 acc[NB];
#pragma unroll
        for (int e = 0; e < NB; e++) {
            u64 a = pk(bias, 0.0f);
            ulonglong2 xv = *((const ulonglong2*)&x_sm[e][s * D_IN]);
            a = f2(xv.x, wih[0], a);
            a = f2(xv.y, wih[1], a);
            const ulonglong2* he = (const ulonglong2*)h_sm[e];
#pragma unroll
            for (int i = 0; i < 16; i++) {
                ulonglong2 hv = he[i];
                a = f2(hv.x, whh[2 * i], a);
                a = f2(hv.y, whh[2 * i + 1], a);
            }
            acc[e] = a;
        }
#pragma unroll
        for (int e = 0; e < NB; e++) {
            float lo, hi; upk(acc[e], lo, hi);
            g_sm[e][tid] = lo + hi;
        }
        __syncthreads();

        // ---- cell/hidden update: thread = one (elem, hidden) pair
        float gi = g_sm[e_up][j_up];
        float gf = g_sm[e_up][j_up + 64];
        float gg = g_sm[e_up][j_up + 128];
        float go = g_sm[e_up][j_up + 192];
        c_state = sigf(gf) * c_state + sigf(gi) * tanhf(gg);
        float h = sigf(go) * tanhf(c_state);
        h_sm[e_up][j_up] = h;
        h1_row[s * HDIM] = h;      // coalesced per warp
        __syncthreads();
    }
}

// ---------------------------------------------------------------------------
// Layer 1 + FC: h1[B,T,64] -> out[B,1]
// ---------------------------------------------------------------------------
__global__ void __launch_bounds__(256) lstm_layer1_fc(
    const float* __restrict__ Wih, const float* __restrict__ Whh,
    const float* __restrict__ bih, const float* __restrict__ bhh,
    const float* __restrict__ Wfc, const float* __restrict__ bfc,
    float* __restrict__ out)
{
    __shared__ float in_sm[2][NB][HDIM];  // double-buffered layer-1 input
    __shared__ float h_sm[NB][HDIM];
    __shared__ float g_sm[NB][GDIM];

    const int tid = threadIdx.x;
    const int b0  = blockIdx.x * NB;

    u64 wih[32], whh[32];
    {
        const ulonglong2* ir = (const ulonglong2*)(Wih + tid * HDIM);
        const ulonglong2* hr = (const ulonglong2*)(Whh + tid * HDIM);
#pragma unroll
        for (int i = 0; i < 16; i++) {
            ulonglong2 v = ir[i];
            wih[2 * i] = v.x; wih[2 * i + 1] = v.y;
        }
#pragma unroll
        for (int i = 0; i < 16; i++) {
            ulonglong2 v = hr[i];
            whh[2 * i] = v.x; whh[2 * i + 1] = v.y;
        }
    }
    const float bias = bih[tid] + bhh[tid];
    const int e_up = tid >> 6, j_up = tid & 63;
    const float* h1_row = g_h1 + ((size_t)(b0 + e_up) * T_STEPS) * HDIM + j_up;

    in_sm[0][e_up][j_up] = h1_row[0];   // step-0 input
    ((float*)h_sm)[tid] = 0.0f;
    float c_state = 0.0f;
    __syncthreads();

    for (int s = 0; s < T_STEPS; s++) {
        const int buf = s & 1;
        // prefetch next step's input into a register (hides DRAM/L2 latency)
        float pre_in = 0.0f;
        if (s + 1 < T_STEPS) pre_in = h1_row[(size_t)(s + 1) * HDIM];

        u64 acc[NB];
#pragma unroll
        for (int e = 0; e < NB; e++) {
            u64 a = pk(bias, 0.0f);
            const ulonglong2* xe = (const ulonglong2*)in_sm[buf][e];
            const ulonglong2* he = (const ulonglong2*)h_sm[e];
#pragma unroll
            for (int i = 0; i < 16; i++) {
                ulonglong2 xv = xe[i];
                a = f2(xv.x, wih[2 * i], a);
                a = f2(xv.y, wih[2 * i + 1], a);
            }
#pragma unroll
            for (int i = 0; i < 16; i++) {
                ulonglong2 hv = he[i];
                a = f2(hv.x, whh[2 * i], a);
                a = f2(hv.y, whh[2 * i + 1], a);
            }
            acc[e] = a;
        }
#pragma unroll
        for (int e = 0; e < NB; e++) {
            float lo, hi; upk(acc[e], lo, hi);
            g_sm[e][tid] = lo + hi;
        }
        __syncthreads();

        float gi = g_sm[e_up][j_up];
        float gf = g_sm[e_up][j_up + 64];
        float gg = g_sm[e_up][j_up + 128];
        float go = g_sm[e_up][j_up + 192];
        c_state = sigf(gf) * c_state + sigf(gi) * tanhf(gg);
        float h = sigf(go) * tanhf(c_state);
        h_sm[e_up][j_up] = h;
        in_sm[buf ^ 1][e_up][j_up] = pre_in;
        __syncthreads();
    }

    // Fused FC on the final hidden state: out[b] = h . Wfc + bfc
    float p = h_sm[e_up][j_up] * Wfc[j_up];
#pragma unroll
    for (int o = 16; o > 0; o >>= 1) p += __shfl_xor_sync(0xffffffffu, p, o);
    const int wid = tid >> 5, lid = tid & 31;
    if (lid == 0) g_sm[0][wid] = p;    // 8 warp partials (2 per batch elem)
    __syncthreads();
    if (tid < NB) out[b0 + tid] = g_sm[0][2 * tid] + g_sm[0][2 * tid + 1] + bfc[0];
}

// ---------------------------------------------------------------------------
extern "C" void kernel_launch(void* const* d_in, const int* in_sizes, int n_in,
                              void* d_out, int out_size)
{
    const float* x    = (const float*)d_in[0];
    const float* Wih0 = (const float*)d_in[1];
    const float* Whh0 = (const float*)d_in[2];
    const float* bih0 = (const float*)d_in[3];
    const float* bhh0 = (const float*)d_in[4];
    const float* Wih1 = (const float*)d_in[5];
    const float* Whh1 = (const float*)d_in[6];
    const float* bih1 = (const float*)d_in[7];
    const float* bhh1 = (const float*)d_in[8];
    const float* Wfc  = (const float*)d_in[9];
    const float* bfc  = (const float*)d_in[10];
    float* out = (float*)d_out;

    dim3 grid(B_TOTAL / NB), block(256);
    lstm_layer0<<<grid, block>>>(x, Wih0, Whh0, bih0, bhh0);
    lstm_layer1_fc<<<grid, block>>>(Wih1, Whh1, bih1, bhh1, Wfc, bfc, out);
}